// round 15
// baseline (speedup 1.0000x reference)
#include <cuda_runtime.h>
#include <math.h>
#include <stdint.h>

#define NROW 4096
#define CH   1024
#define MQ   8
#define KQ   2048
#define DQ   128
#define CAP  64
#define WPB  4      // 128-thread blocks: floor(21 regs-limited warps / 4) = 5 blocks
                    // = 20 warps/SM vs 16 with 256-thread blocks. Body untouched.

// Per-(level,m) max_k |c_k|^2, as ordered uint (floats >= 0). Zero-initialized at
// module load; atomicMax over a fixed input set is idempotent across graph replays.
static __device__ unsigned g_cm2[2][MQ];

// One warp per 8 consecutive k: 8 interleaved butterflies (MLP=8), one atomicMax.
// (Measured 8.16us in R12 vs ~20us for the 1-k/warp version.)
__global__ void cm2_k(const float* __restrict__ cb0, const float* __restrict__ cb1) {
    const int level = blockIdx.y;
    const float* cb = level ? cb1 : cb0;
    const int w    = (blockIdx.x * blockDim.x + threadIdx.x) >> 5;
    const int lane = threadIdx.x & 31;
    if (w >= (MQ * KQ) / 8) return;
    float s[8];
#pragma unroll
    for (int r = 0; r < 8; r++) {
        float4 v = reinterpret_cast<const float4*>(cb)[(size_t)(w * 8 + r) * (DQ / 4) + lane];
        s[r] = v.x * v.x + v.y * v.y + v.z * v.z + v.w * v.w;
    }
#pragma unroll
    for (int o = 16; o; o >>= 1)
#pragma unroll
        for (int r = 0; r < 8; r++) s[r] += __shfl_xor_sync(0xffffffffu, s[r], o);
    if (lane == 0) {
        float mx = s[0];
#pragma unroll
        for (int r = 1; r < 8; r++) mx = fmaxf(mx, s[r]);
        atomicMax(&g_cm2[level][(w * 8) >> 11], __float_as_uint(mx));
    }
}

__device__ __forceinline__ float warp_sum(float v) {
#pragma unroll
    for (int o = 16; o; o >>= 1) v += __shfl_xor_sync(0xffffffffu, v, o);
    return v;
}
__device__ __forceinline__ float warp_max(float v) {
#pragma unroll
    for (int o = 16; o; o >>= 1) v = fmaxf(v, __shfl_xor_sync(0xffffffffu, v, o));
    return v;
}

// One warp, one (n,m) row, one level: scan u (2048 floats, kept in regs),
// gumbel-max pruning, fp32 scoring of the few candidates, fp64 re-score only
// on near-ties. (Byte-for-byte the R2/R14 source — measured 150.8us @ 16 warps.)
__device__ __forceinline__ int pick_code(
    float4 z, float x2, float t,
    const float* __restrict__ cbm,   // codebook + m*K*D
    float cm2,
    const float4* __restrict__ u4row,
    int lane, int* s_cnt, int* s_kl, float* s_ul)
{
    if (lane == 0) *s_cnt = 0;

    // Pass 1: stream u row into registers (16 LDG.128/lane, front-batched) + running max.
    float4 ur[16];
    float umax = 0.0f;
#pragma unroll
    for (int j = 0; j < 16; j++) {
        ur[j] = u4row[j * 32 + lane];
        umax = fmaxf(umax, fmaxf(fmaxf(ur[j].x, ur[j].y), fmaxf(ur[j].z, ur[j].w)));
    }
    umax = warp_max(umax);

    const float SCALE = 45.25483399593904f;   // sqrt(2048)
    const float EPSF  = 1e-6f;
    const float HI    = (float)(1.0 - 1e-6);

    // Rigorous spread bound of logit over k (Cauchy-Schwarz), inflated for fp noise.
    const float cmax = sqrtf(cm2);
    float delta = (t / SCALE) * (4.0f * sqrtf(x2) * cmax + cm2);
    delta = delta * 1.01f + 0.02f;

    // g(u) = -log(-log u) is monotone in u: candidate iff u >= uthr.
    float ucm  = fminf(fmaxf(umax, EPSF), HI);
    float gm   = -logf(-logf(ucm));
    float uthr = expf(-expf(-(gm - delta))) * (1.0f - 1e-5f);
    uthr = fminf(uthr, umax);

    __syncwarp();
    // Pass 2: slab-level warp-uniform skip via ballot; rare pushes to smem list.
#pragma unroll
    for (int j = 0; j < 16; j++) {
        const float4 v = ur[j];
        unsigned p = (unsigned)(v.x >= uthr) | ((unsigned)(v.y >= uthr) << 1)
                   | ((unsigned)(v.z >= uthr) << 2) | ((unsigned)(v.w >= uthr) << 3);
        if (__ballot_sync(0xffffffffu, p != 0u)) {
            const int kb = (j * 32 + lane) * 4;
            if (p & 1u) { int q = atomicAdd(s_cnt, 1); if (q < CAP) { s_kl[q] = kb + 0; s_ul[q] = v.x; } }
            if (p & 2u) { int q = atomicAdd(s_cnt, 1); if (q < CAP) { s_kl[q] = kb + 1; s_ul[q] = v.y; } }
            if (p & 4u) { int q = atomicAdd(s_cnt, 1); if (q < CAP) { s_kl[q] = kb + 2; s_ul[q] = v.z; } }
            if (p & 8u) { int q = atomicAdd(s_cnt, 1); if (q < CAP) { s_kl[q] = kb + 3; s_ul[q] = v.w; } }
        }
    }
    __syncwarp();
    int cnt = *s_cnt;
    if (cnt > CAP) cnt = CAP;              // statistically unreachable
    if (cnt <= 1) return s_kl[0];          // max element always passes -> cnt >= 1

    // Fast scoring: 4-wide ILP batches, fp32 gumbel (MUFU). Track top-2 gap.
    float best_s = -3.4e38f, sec_s = -3.4e38f;
    int   best_k = 0;
    for (int base = 0; base < cnt; base += 4) {
        float pq[4], qq[4]; int kk[4];
#pragma unroll
        for (int i4 = 0; i4 < 4; i4++) {
            int i = base + i4; if (i > cnt - 1) i = cnt - 1;
            int k = s_kl[i]; kk[i4] = k;
            float4 c = reinterpret_cast<const float4*>(cbm)[(size_t)k * (DQ / 4) + lane];
            pq[i4] = z.x * c.x + z.y * c.y + z.z * c.z + z.w * c.w;
            qq[i4] = c.x * c.x + c.y * c.y + c.z * c.z + c.w * c.w;
        }
#pragma unroll
        for (int o = 16; o; o >>= 1) {                 // interleaved butterflies (ILP)
#pragma unroll
            for (int i4 = 0; i4 < 4; i4++) {
                pq[i4] += __shfl_xor_sync(0xffffffffu, pq[i4], o);
                qq[i4] += __shfl_xor_sync(0xffffffffu, qq[i4], o);
            }
        }
#pragma unroll
        for (int i4 = 0; i4 < 4; i4++) {
            int i = base + i4; if (i >= cnt) break;
            float uc = fminf(fmaxf(s_ul[i], EPSF), HI);
            float g  = -logf(-logf(uc));
            float dist  = __fadd_rn(__fadd_rn(x2, qq[i4]), -__fmul_rn(2.0f, pq[i4]));
            float logit = __fmul_rn(__fdiv_rn(-dist, SCALE), t);
            float sc    = __fadd_rn(logit, g);
            int   k     = kk[i4];
            if (sc > best_s || (sc == best_s && k < best_k)) {
                sec_s = best_s; best_s = sc; best_k = k;
            } else if (sc > sec_s) sec_s = sc;
        }
    }

    // Refinement (rare, ~1e-3 of rows): exact fp64-gumbel rescore, identical to the
    // reference-faithful formula. Margin 3e-3 >> fp32/fast-math log error (<=1e-5).
    if (best_s - sec_s < 3e-3f) {
        best_s = -3.4e38f; best_k = 0;
        for (int i = 0; i < cnt; i++) {
            const int k = s_kl[i];
            float4 c = reinterpret_cast<const float4*>(cbm)[(size_t)k * (DQ / 4) + lane];
            float p = warp_sum(z.x * c.x + z.y * c.y + z.z * c.z + z.w * c.w);
            float q = warp_sum(c.x * c.x + c.y * c.y + c.z * c.z + c.w * c.w);
            double ucl = (double)fminf(fmaxf(s_ul[i], EPSF), HI);
            float  g   = (float)(-log(-log(ucl)));
            float dist  = __fadd_rn(__fadd_rn(x2, q), -__fmul_rn(2.0f, p));
            float logit = __fmul_rn(__fdiv_rn(-dist, SCALE), t);
            float sc    = __fadd_rn(logit, g);
            if (sc > best_s || (sc == best_s && k < best_k)) { best_s = sc; best_k = k; }
        }
    }
    __syncwarp();
    return best_k;
}

__global__ void __launch_bounds__(WPB * 32) umgm_kernel(
    const float* __restrict__ x,
    const float* __restrict__ cb0,
    const float* __restrict__ cb1,
    const float* __restrict__ t0p,
    const float* __restrict__ t1p,
    const float* __restrict__ u0,
    const float* __restrict__ u1,
    float* __restrict__ out)
{
    __shared__ int   s_cnt[WPB];
    __shared__ int   s_k[WPB][CAP];
    __shared__ float s_u[WPB][CAP];
    const int w    = threadIdx.x >> 5;
    const int lane = threadIdx.x & 31;
    const int row  = blockIdx.x * WPB + w;   // row = n*M + m (matches u layout)
    const int n    = row >> 3;
    const int m    = row & 7;
    const float EPSF = 1e-6f;

    // z row (dims [4*lane, 4*lane+4)) and |z|^2
    float4 z = reinterpret_cast<const float4*>(x + (size_t)n * CH + m * DQ)[lane];
    float x2 = warp_sum(z.x * z.x + z.y * z.y + z.z * z.z + z.w * z.w);

    const float* cbm0 = cb0 + (size_t)m * KQ * DQ;
    const float* cbm1 = cb1 + (size_t)m * KQ * DQ;

    // ---- level 0 ----
    int k0 = pick_code(z, x2, fmaxf(t0p[m], EPSF), cbm0,
                       __uint_as_float(g_cm2[0][m]),
                       reinterpret_cast<const float4*>(u0) + (size_t)row * (KQ / 4),
                       lane, &s_cnt[w], s_k[w], s_u[w]);
    float4 c0 = reinterpret_cast<const float4*>(cbm0)[(size_t)k0 * (DQ / 4) + lane];

    // residual x1 = x - deq0 (bitwise same op as reference)
    float4 z1 = make_float4(z.x - c0.x, z.y - c0.y, z.z - c0.z, z.w - c0.w);
    float x2b = warp_sum(z1.x * z1.x + z1.y * z1.y + z1.z * z1.z + z1.w * z1.w);

    // ---- level 1 ----
    int k1 = pick_code(z1, x2b, fmaxf(t1p[m], EPSF), cbm1,
                       __uint_as_float(g_cm2[1][m]),
                       reinterpret_cast<const float4*>(u1) + (size_t)row * (KQ / 4),
                       lane, &s_cnt[w], s_k[w], s_u[w]);
    float4 c1 = reinterpret_cast<const float4*>(cbm1)[(size_t)k1 * (DQ / 4) + lane];

    // xHat = deq0 + deq1
    float4 o = make_float4(c0.x + c1.x, c0.y + c1.y, c0.z + c1.z, c0.w + c1.w);
    reinterpret_cast<float4*>(out + (size_t)n * CH + m * DQ)[lane] = o;
}

extern "C" void kernel_launch(void* const* d_in, const int* in_sizes, int n_in,
                              void* d_out, int out_size) {
    const float *x = nullptr, *cb0 = nullptr, *cb1 = nullptr,
                *t0 = nullptr, *t1 = nullptr, *u0 = nullptr, *u1 = nullptr;
    for (int i = 0; i < n_in; i++) {
        const float* p = (const float*)d_in[i];
        const long sz = in_sizes[i];
        if      (sz == (long)NROW * CH)        { x = p; }
        else if (sz == (long)MQ * KQ * DQ)     { if (!cb0) cb0 = p; else cb1 = p; }
        else if (sz == (long)MQ)               { if (!t0)  t0  = p; else t1  = p; }
        else if (sz == (long)NROW * MQ * KQ)   { if (!u0)  u0  = p; else u1  = p; }
    }
    float* out = (float*)d_out;
    (void)out_size;

    dim3 gc((MQ * KQ) / (8 * 8), 2);       // 8 k's per warp, 8 warps/block
    cm2_k<<<gc, 256>>>(cb0, cb1);
    umgm_kernel<<<(NROW * MQ) / WPB, WPB * 32>>>(x, cb0, cb1, t0, t1, u0, u1, out);
}

// round 16
// speedup vs baseline: 1.0138x; 1.0138x over previous
#include <cuda_runtime.h>
#include <math.h>
#include <stdint.h>

#define NROW 4096
#define CH   1024
#define MQ   8
#define KQ   2048
#define DQ   128
#define CAP  64

// Per-(level,m) max_k |c_k|^2, as ordered uint (floats >= 0). Zero-initialized at
// module load; atomicMax over a fixed input set is idempotent across graph replays.
static __device__ unsigned g_cm2[2][MQ];

// One warp per 8 consecutive k: 8 interleaved butterflies (MLP=8), one atomicMax.
// (Measured 8.16us in R12 vs ~20us for the 1-k/warp version.)
__global__ void cm2_k(const float* __restrict__ cb0, const float* __restrict__ cb1) {
    const int level = blockIdx.y;
    const float* cb = level ? cb1 : cb0;
    const int w    = (blockIdx.x * blockDim.x + threadIdx.x) >> 5;
    const int lane = threadIdx.x & 31;
    if (w >= (MQ * KQ) / 8) return;
    float s[8];
#pragma unroll
    for (int r = 0; r < 8; r++) {
        float4 v = reinterpret_cast<const float4*>(cb)[(size_t)(w * 8 + r) * (DQ / 4) + lane];
        s[r] = v.x * v.x + v.y * v.y + v.z * v.z + v.w * v.w;
    }
#pragma unroll
    for (int o = 16; o; o >>= 1)
#pragma unroll
        for (int r = 0; r < 8; r++) s[r] += __shfl_xor_sync(0xffffffffu, s[r], o);
    if (lane == 0) {
        float mx = s[0];
#pragma unroll
        for (int r = 1; r < 8; r++) mx = fmaxf(mx, s[r]);
        atomicMax(&g_cm2[level][(w * 8) >> 11], __float_as_uint(mx));
    }
}

__device__ __forceinline__ float warp_sum(float v) {
#pragma unroll
    for (int o = 16; o; o >>= 1) v += __shfl_xor_sync(0xffffffffu, v, o);
    return v;
}
__device__ __forceinline__ float warp_max(float v) {
#pragma unroll
    for (int o = 16; o; o >>= 1) v = fmaxf(v, __shfl_xor_sync(0xffffffffu, v, o));
    return v;
}

// One warp, one (n,m) row, one level: scan u (2048 floats, kept in regs),
// gumbel-max pruning, fp32 scoring of the few candidates, fp64 re-score only
// on near-ties. (Byte-for-byte the R2/R14 source — measured 150.8us.)
__device__ __forceinline__ int pick_code(
    float4 z, float x2, float t,
    const float* __restrict__ cbm,   // codebook + m*K*D
    float cm2,
    const float4* __restrict__ u4row,
    int lane, int* s_cnt, int* s_kl, float* s_ul)
{
    if (lane == 0) *s_cnt = 0;

    // Pass 1: stream u row into registers (16 LDG.128/lane, front-batched) + running max.
    float4 ur[16];
    float umax = 0.0f;
#pragma unroll
    for (int j = 0; j < 16; j++) {
        ur[j] = u4row[j * 32 + lane];
        umax = fmaxf(umax, fmaxf(fmaxf(ur[j].x, ur[j].y), fmaxf(ur[j].z, ur[j].w)));
    }
    umax = warp_max(umax);

    const float SCALE = 45.25483399593904f;   // sqrt(2048)
    const float EPSF  = 1e-6f;
    const float HI    = (float)(1.0 - 1e-6);

    // Rigorous spread bound of logit over k (Cauchy-Schwarz), inflated for fp noise.
    const float cmax = sqrtf(cm2);
    float delta = (t / SCALE) * (4.0f * sqrtf(x2) * cmax + cm2);
    delta = delta * 1.01f + 0.02f;

    // g(u) = -log(-log u) is monotone in u: candidate iff u >= uthr.
    float ucm  = fminf(fmaxf(umax, EPSF), HI);
    float gm   = -logf(-logf(ucm));
    float uthr = expf(-expf(-(gm - delta))) * (1.0f - 1e-5f);
    uthr = fminf(uthr, umax);

    __syncwarp();
    // Pass 2: slab-level warp-uniform skip via ballot; rare pushes to smem list.
#pragma unroll
    for (int j = 0; j < 16; j++) {
        const float4 v = ur[j];
        unsigned p = (unsigned)(v.x >= uthr) | ((unsigned)(v.y >= uthr) << 1)
                   | ((unsigned)(v.z >= uthr) << 2) | ((unsigned)(v.w >= uthr) << 3);
        if (__ballot_sync(0xffffffffu, p != 0u)) {
            const int kb = (j * 32 + lane) * 4;
            if (p & 1u) { int q = atomicAdd(s_cnt, 1); if (q < CAP) { s_kl[q] = kb + 0; s_ul[q] = v.x; } }
            if (p & 2u) { int q = atomicAdd(s_cnt, 1); if (q < CAP) { s_kl[q] = kb + 1; s_ul[q] = v.y; } }
            if (p & 4u) { int q = atomicAdd(s_cnt, 1); if (q < CAP) { s_kl[q] = kb + 2; s_ul[q] = v.z; } }
            if (p & 8u) { int q = atomicAdd(s_cnt, 1); if (q < CAP) { s_kl[q] = kb + 3; s_ul[q] = v.w; } }
        }
    }
    __syncwarp();
    int cnt = *s_cnt;
    if (cnt > CAP) cnt = CAP;              // statistically unreachable
    if (cnt <= 1) return s_kl[0];          // max element always passes -> cnt >= 1

    // Fast scoring: 4-wide ILP batches, fp32 gumbel (MUFU). Track top-2 gap.
    float best_s = -3.4e38f, sec_s = -3.4e38f;
    int   best_k = 0;
    for (int base = 0; base < cnt; base += 4) {
        float pq[4], qq[4]; int kk[4];
#pragma unroll
        for (int i4 = 0; i4 < 4; i4++) {
            int i = base + i4; if (i > cnt - 1) i = cnt - 1;
            int k = s_kl[i]; kk[i4] = k;
            float4 c = reinterpret_cast<const float4*>(cbm)[(size_t)k * (DQ / 4) + lane];
            pq[i4] = z.x * c.x + z.y * c.y + z.z * c.z + z.w * c.w;
            qq[i4] = c.x * c.x + c.y * c.y + c.z * c.z + c.w * c.w;
        }
#pragma unroll
        for (int o = 16; o; o >>= 1) {                 // interleaved butterflies (ILP)
#pragma unroll
            for (int i4 = 0; i4 < 4; i4++) {
                pq[i4] += __shfl_xor_sync(0xffffffffu, pq[i4], o);
                qq[i4] += __shfl_xor_sync(0xffffffffu, qq[i4], o);
            }
        }
#pragma unroll
        for (int i4 = 0; i4 < 4; i4++) {
            int i = base + i4; if (i >= cnt) break;
            float uc = fminf(fmaxf(s_ul[i], EPSF), HI);
            float g  = -logf(-logf(uc));
            float dist  = __fadd_rn(__fadd_rn(x2, qq[i4]), -__fmul_rn(2.0f, pq[i4]));
            float logit = __fmul_rn(__fdiv_rn(-dist, SCALE), t);
            float sc    = __fadd_rn(logit, g);
            int   k     = kk[i4];
            if (sc > best_s || (sc == best_s && k < best_k)) {
                sec_s = best_s; best_s = sc; best_k = k;
            } else if (sc > sec_s) sec_s = sc;
        }
    }

    // Refinement (rare, ~1e-3 of rows): exact fp64-gumbel rescore, identical to the
    // reference-faithful formula. Margin 3e-3 >> fp32/fast-math log error (<=1e-5).
    if (best_s - sec_s < 3e-3f) {
        best_s = -3.4e38f; best_k = 0;
        for (int i = 0; i < cnt; i++) {
            const int k = s_kl[i];
            float4 c = reinterpret_cast<const float4*>(cbm)[(size_t)k * (DQ / 4) + lane];
            float p = warp_sum(z.x * c.x + z.y * c.y + z.z * c.z + z.w * c.w);
            float q = warp_sum(c.x * c.x + c.y * c.y + c.z * c.z + c.w * c.w);
            double ucl = (double)fminf(fmaxf(s_ul[i], EPSF), HI);
            float  g   = (float)(-log(-log(ucl)));
            float dist  = __fadd_rn(__fadd_rn(x2, q), -__fmul_rn(2.0f, p));
            float logit = __fmul_rn(__fdiv_rn(-dist, SCALE), t);
            float sc    = __fadd_rn(logit, g);
            if (sc > best_s || (sc == best_s && k < best_k)) { best_s = sc; best_k = k; }
        }
    }
    __syncwarp();
    return best_k;
}

// NOTE: __launch_bounds__(256) is kept — the exact compilation contract of the
// 94-reg R14 schedule — but the kernel is LAUNCHED with 128-thread blocks.
// 4-warp blocks pack 5-per-SM against the 21-warp register limit (20 warps/SM
// vs 16 with 256-thread blocks). Only the row constant changes (8 -> 4).
__global__ void __launch_bounds__(256) umgm_kernel(
    const float* __restrict__ x,
    const float* __restrict__ cb0,
    const float* __restrict__ cb1,
    const float* __restrict__ t0p,
    const float* __restrict__ t1p,
    const float* __restrict__ u0,
    const float* __restrict__ u1,
    float* __restrict__ out)
{
    __shared__ int   s_cnt[8];
    __shared__ int   s_k[8][CAP];
    __shared__ float s_u[8][CAP];
    const int w    = threadIdx.x >> 5;
    const int lane = threadIdx.x & 31;
    const int row  = blockIdx.x * 4 + w;   // row = n*M + m (matches u layout)
    const int n    = row >> 3;
    const int m    = row & 7;
    const float EPSF = 1e-6f;

    // z row (dims [4*lane, 4*lane+4)) and |z|^2
    float4 z = reinterpret_cast<const float4*>(x + (size_t)n * CH + m * DQ)[lane];
    float x2 = warp_sum(z.x * z.x + z.y * z.y + z.z * z.z + z.w * z.w);

    const float* cbm0 = cb0 + (size_t)m * KQ * DQ;
    const float* cbm1 = cb1 + (size_t)m * KQ * DQ;

    // ---- level 0 ----
    int k0 = pick_code(z, x2, fmaxf(t0p[m], EPSF), cbm0,
                       __uint_as_float(g_cm2[0][m]),
                       reinterpret_cast<const float4*>(u0) + (size_t)row * (KQ / 4),
                       lane, &s_cnt[w], s_k[w], s_u[w]);
    float4 c0 = reinterpret_cast<const float4*>(cbm0)[(size_t)k0 * (DQ / 4) + lane];

    // residual x1 = x - deq0 (bitwise same op as reference)
    float4 z1 = make_float4(z.x - c0.x, z.y - c0.y, z.z - c0.z, z.w - c0.w);
    float x2b = warp_sum(z1.x * z1.x + z1.y * z1.y + z1.z * z1.z + z1.w * z1.w);

    // ---- level 1 ----
    int k1 = pick_code(z1, x2b, fmaxf(t1p[m], EPSF), cbm1,
                       __uint_as_float(g_cm2[1][m]),
                       reinterpret_cast<const float4*>(u1) + (size_t)row * (KQ / 4),
                       lane, &s_cnt[w], s_k[w], s_u[w]);
    float4 c1 = reinterpret_cast<const float4*>(cbm1)[(size_t)k1 * (DQ / 4) + lane];

    // xHat = deq0 + deq1
    float4 o = make_float4(c0.x + c1.x, c0.y + c1.y, c0.z + c1.z, c0.w + c1.w);
    reinterpret_cast<float4*>(out + (size_t)n * CH + m * DQ)[lane] = o;
}

extern "C" void kernel_launch(void* const* d_in, const int* in_sizes, int n_in,
                              void* d_out, int out_size) {
    const float *x = nullptr, *cb0 = nullptr, *cb1 = nullptr,
                *t0 = nullptr, *t1 = nullptr, *u0 = nullptr, *u1 = nullptr;
    for (int i = 0; i < n_in; i++) {
        const float* p = (const float*)d_in[i];
        const long sz = in_sizes[i];
        if      (sz == (long)NROW * CH)        { x = p; }
        else if (sz == (long)MQ * KQ * DQ)     { if (!cb0) cb0 = p; else cb1 = p; }
        else if (sz == (long)MQ)               { if (!t0)  t0  = p; else t1  = p; }
        else if (sz == (long)NROW * MQ * KQ)   { if (!u0)  u0  = p; else u1  = p; }
    }
    float* out = (float*)d_out;
    (void)out_size;

    dim3 gc((MQ * KQ) / (8 * 8), 2);       // 8 k's per warp, 8 warps/block
    cm2_k<<<gc, 256>>>(cb0, cb1);
    umgm_kernel<<<(NROW * MQ) / 4, 128>>>(x, cb0, cb1, t0, t1, u0, u1, out);
}

// round 17
// speedup vs baseline: 1.2721x; 1.2547x over previous
#include <cuda_runtime.h>
#include <math.h>
#include <stdint.h>

#define NROW 4096
#define CH   1024
#define MQ   8
#define KQ   2048
#define DQ   128
#define CAP  64

// Per-(level,m) max_k |c_k|^2, as ordered uint (floats >= 0). Zero-initialized at
// module load; atomicMax over a fixed input set is idempotent across graph replays.
static __device__ unsigned g_cm2[2][MQ];

// One warp per 8 consecutive k: 8 interleaved butterflies (MLP=8), one atomicMax.
// (Measured 8.16us in R12; do not touch.)
__global__ void cm2_k(const float* __restrict__ cb0, const float* __restrict__ cb1) {
    const int level = blockIdx.y;
    const float* cb = level ? cb1 : cb0;
    const int w    = (blockIdx.x * blockDim.x + threadIdx.x) >> 5;
    const int lane = threadIdx.x & 31;
    if (w >= (MQ * KQ) / 8) return;
    float s[8];
#pragma unroll
    for (int r = 0; r < 8; r++) {
        float4 v = reinterpret_cast<const float4*>(cb)[(size_t)(w * 8 + r) * (DQ / 4) + lane];
        s[r] = v.x * v.x + v.y * v.y + v.z * v.z + v.w * v.w;
    }
#pragma unroll
    for (int o = 16; o; o >>= 1)
#pragma unroll
        for (int r = 0; r < 8; r++) s[r] += __shfl_xor_sync(0xffffffffu, s[r], o);
    if (lane == 0) {
        float mx = s[0];
#pragma unroll
        for (int r = 1; r < 8; r++) mx = fmaxf(mx, s[r]);
        atomicMax(&g_cm2[level][(w * 8) >> 11], __float_as_uint(mx));
    }
}

__device__ __forceinline__ float warp_sum(float v) {
#pragma unroll
    for (int o = 16; o; o >>= 1) v += __shfl_xor_sync(0xffffffffu, v, o);
    return v;
}
__device__ __forceinline__ float warp_max(float v) {
#pragma unroll
    for (int o = 16; o; o >>= 1) v = fmaxf(v, __shfl_xor_sync(0xffffffffu, v, o));
    return v;
}

// One warp, one (n,m) row, one level: scan u (2048 floats, kept in regs),
// gumbel-max pruning, fp32 scoring of the few candidates, fp64 re-score only
// on near-ties. (R14 source; the ONLY change is __ldcs on the u burst —
// streaming/evict-first so the 537MB u stream stops evicting the 16MB of
// codebooks from L2, shortening the dependent-gather tail.)
__device__ __forceinline__ int pick_code(
    float4 z, float x2, float t,
    const float* __restrict__ cbm,   // codebook + m*K*D
    float cm2,
    const float4* __restrict__ u4row,
    int lane, int* s_cnt, int* s_kl, float* s_ul)
{
    if (lane == 0) *s_cnt = 0;

    // Pass 1: stream u row into registers (16 LDG.128/lane, front-batched,
    // evict-first) + running max.
    float4 ur[16];
    float umax = 0.0f;
#pragma unroll
    for (int j = 0; j < 16; j++) {
        ur[j] = __ldcs(&u4row[j * 32 + lane]);
        umax = fmaxf(umax, fmaxf(fmaxf(ur[j].x, ur[j].y), fmaxf(ur[j].z, ur[j].w)));
    }
    umax = warp_max(umax);

    const float SCALE = 45.25483399593904f;   // sqrt(2048)
    const float EPSF  = 1e-6f;
    const float HI    = (float)(1.0 - 1e-6);

    // Rigorous spread bound of logit over k (Cauchy-Schwarz), inflated for fp noise.
    const float cmax = sqrtf(cm2);
    float delta = (t / SCALE) * (4.0f * sqrtf(x2) * cmax + cm2);
    delta = delta * 1.01f + 0.02f;

    // g(u) = -log(-log u) is monotone in u: candidate iff u >= uthr.
    float ucm  = fminf(fmaxf(umax, EPSF), HI);
    float gm   = -logf(-logf(ucm));
    float uthr = expf(-expf(-(gm - delta))) * (1.0f - 1e-5f);
    uthr = fminf(uthr, umax);

    __syncwarp();
    // Pass 2: slab-level warp-uniform skip via ballot; rare pushes to smem list.
#pragma unroll
    for (int j = 0; j < 16; j++) {
        const float4 v = ur[j];
        unsigned p = (unsigned)(v.x >= uthr) | ((unsigned)(v.y >= uthr) << 1)
                   | ((unsigned)(v.z >= uthr) << 2) | ((unsigned)(v.w >= uthr) << 3);
        if (__ballot_sync(0xffffffffu, p != 0u)) {
            const int kb = (j * 32 + lane) * 4;
            if (p & 1u) { int q = atomicAdd(s_cnt, 1); if (q < CAP) { s_kl[q] = kb + 0; s_ul[q] = v.x; } }
            if (p & 2u) { int q = atomicAdd(s_cnt, 1); if (q < CAP) { s_kl[q] = kb + 1; s_ul[q] = v.y; } }
            if (p & 4u) { int q = atomicAdd(s_cnt, 1); if (q < CAP) { s_kl[q] = kb + 2; s_ul[q] = v.z; } }
            if (p & 8u) { int q = atomicAdd(s_cnt, 1); if (q < CAP) { s_kl[q] = kb + 3; s_ul[q] = v.w; } }
        }
    }
    __syncwarp();
    int cnt = *s_cnt;
    if (cnt > CAP) cnt = CAP;              // statistically unreachable
    if (cnt <= 1) return s_kl[0];          // max element always passes -> cnt >= 1

    // Fast scoring: 4-wide ILP batches, fp32 gumbel (MUFU). Track top-2 gap.
    float best_s = -3.4e38f, sec_s = -3.4e38f;
    int   best_k = 0;
    for (int base = 0; base < cnt; base += 4) {
        float pq[4], qq[4]; int kk[4];
#pragma unroll
        for (int i4 = 0; i4 < 4; i4++) {
            int i = base + i4; if (i > cnt - 1) i = cnt - 1;
            int k = s_kl[i]; kk[i4] = k;
            float4 c = reinterpret_cast<const float4*>(cbm)[(size_t)k * (DQ / 4) + lane];
            pq[i4] = z.x * c.x + z.y * c.y + z.z * c.z + z.w * c.w;
            qq[i4] = c.x * c.x + c.y * c.y + c.z * c.z + c.w * c.w;
        }
#pragma unroll
        for (int o = 16; o; o >>= 1) {                 // interleaved butterflies (ILP)
#pragma unroll
            for (int i4 = 0; i4 < 4; i4++) {
                pq[i4] += __shfl_xor_sync(0xffffffffu, pq[i4], o);
                qq[i4] += __shfl_xor_sync(0xffffffffu, qq[i4], o);
            }
        }
#pragma unroll
        for (int i4 = 0; i4 < 4; i4++) {
            int i = base + i4; if (i >= cnt) break;
            float uc = fminf(fmaxf(s_ul[i], EPSF), HI);
            float g  = -logf(-logf(uc));
            float dist  = __fadd_rn(__fadd_rn(x2, qq[i4]), -__fmul_rn(2.0f, pq[i4]));
            float logit = __fmul_rn(__fdiv_rn(-dist, SCALE), t);
            float sc    = __fadd_rn(logit, g);
            int   k     = kk[i4];
            if (sc > best_s || (sc == best_s && k < best_k)) {
                sec_s = best_s; best_s = sc; best_k = k;
            } else if (sc > sec_s) sec_s = sc;
        }
    }

    // Refinement (rare, ~1e-3 of rows): exact fp64-gumbel rescore, identical to the
    // reference-faithful formula. Margin 3e-3 >> fp32/fast-math log error (<=1e-5).
    if (best_s - sec_s < 3e-3f) {
        best_s = -3.4e38f; best_k = 0;
        for (int i = 0; i < cnt; i++) {
            const int k = s_kl[i];
            float4 c = reinterpret_cast<const float4*>(cbm)[(size_t)k * (DQ / 4) + lane];
            float p = warp_sum(z.x * c.x + z.y * c.y + z.z * c.z + z.w * c.w);
            float q = warp_sum(c.x * c.x + c.y * c.y + c.z * c.z + c.w * c.w);
            double ucl = (double)fminf(fmaxf(s_ul[i], EPSF), HI);
            float  g   = (float)(-log(-log(ucl)));
            float dist  = __fadd_rn(__fadd_rn(x2, q), -__fmul_rn(2.0f, p));
            float logit = __fmul_rn(__fdiv_rn(-dist, SCALE), t);
            float sc    = __fadd_rn(logit, g);
            if (sc > best_s || (sc == best_s && k < best_k)) { best_s = sc; best_k = k; }
        }
    }
    __syncwarp();
    return best_k;
}

__global__ void __launch_bounds__(256) umgm_kernel(
    const float* __restrict__ x,
    const float* __restrict__ cb0,
    const float* __restrict__ cb1,
    const float* __restrict__ t0p,
    const float* __restrict__ t1p,
    const float* __restrict__ u0,
    const float* __restrict__ u1,
    float* __restrict__ out)
{
    __shared__ int   s_cnt[8];
    __shared__ int   s_k[8][CAP];
    __shared__ float s_u[8][CAP];
    const int w    = threadIdx.x >> 5;
    const int lane = threadIdx.x & 31;
    const int row  = blockIdx.x * 8 + w;   // row = n*M + m (matches u layout)
    const int n    = row >> 3;
    const int m    = row & 7;
    const float EPSF = 1e-6f;

    // z row (dims [4*lane, 4*lane+4)) and |z|^2
    float4 z = reinterpret_cast<const float4*>(x + (size_t)n * CH + m * DQ)[lane];
    float x2 = warp_sum(z.x * z.x + z.y * z.y + z.z * z.z + z.w * z.w);

    const float* cbm0 = cb0 + (size_t)m * KQ * DQ;
    const float* cbm1 = cb1 + (size_t)m * KQ * DQ;

    // ---- level 0 ----
    int k0 = pick_code(z, x2, fmaxf(t0p[m], EPSF), cbm0,
                       __uint_as_float(g_cm2[0][m]),
                       reinterpret_cast<const float4*>(u0) + (size_t)row * (KQ / 4),
                       lane, &s_cnt[w], s_k[w], s_u[w]);
    float4 c0 = reinterpret_cast<const float4*>(cbm0)[(size_t)k0 * (DQ / 4) + lane];

    // residual x1 = x - deq0 (bitwise same op as reference)
    float4 z1 = make_float4(z.x - c0.x, z.y - c0.y, z.z - c0.z, z.w - c0.w);
    float x2b = warp_sum(z1.x * z1.x + z1.y * z1.y + z1.z * z1.z + z1.w * z1.w);

    // ---- level 1 ----
    int k1 = pick_code(z1, x2b, fmaxf(t1p[m], EPSF), cbm1,
                       __uint_as_float(g_cm2[1][m]),
                       reinterpret_cast<const float4*>(u1) + (size_t)row * (KQ / 4),
                       lane, &s_cnt[w], s_k[w], s_u[w]);
    float4 c1 = reinterpret_cast<const float4*>(cbm1)[(size_t)k1 * (DQ / 4) + lane];

    // xHat = deq0 + deq1
    float4 o = make_float4(c0.x + c1.x, c0.y + c1.y, c0.z + c1.z, c0.w + c1.w);
    reinterpret_cast<float4*>(out + (size_t)n * CH + m * DQ)[lane] = o;
}

extern "C" void kernel_launch(void* const* d_in, const int* in_sizes, int n_in,
                              void* d_out, int out_size) {
    const float *x = nullptr, *cb0 = nullptr, *cb1 = nullptr,
                *t0 = nullptr, *t1 = nullptr, *u0 = nullptr, *u1 = nullptr;
    for (int i = 0; i < n_in; i++) {
        const float* p = (const float*)d_in[i];
        const long sz = in_sizes[i];
        if      (sz == (long)NROW * CH)        { x = p; }
        else if (sz == (long)MQ * KQ * DQ)     { if (!cb0) cb0 = p; else cb1 = p; }
        else if (sz == (long)MQ)               { if (!t0)  t0  = p; else t1  = p; }
        else if (sz == (long)NROW * MQ * KQ)   { if (!u0)  u0  = p; else u1  = p; }
    }
    float* out = (float*)d_out;
    (void)out_size;

    dim3 gc((MQ * KQ) / (8 * 8), 2);       // 8 k's per warp, 8 warps/block
    cm2_k<<<gc, 256>>>(cb0, cb1);
    umgm_kernel<<<(NROW * MQ) / 8, 256>>>(x, cb0, cb1, t0, t1, u0, u1, out);
}